// round 6
// baseline (speedup 1.0000x reference)
#include <cuda_runtime.h>
#include <cstdint>

#define NMAX 50000
#define EMAX 1600000
#define D 128
#define WPAD 132   // W smem row pad (words)
#define APAD 66    // A smem row pad (words): 64 nodes + 2
#define SCAN_T 1024

typedef unsigned long long ull;

// Scratch (device globals: no runtime allocation allowed)
__device__ int   g_is64;
__device__ int   g_csr_src[EMAX];
__device__ int   g_degi[NMAX];
__device__ int   g_row_start[NMAX + 1];
__device__ int   g_cursor[NMAX];
__device__ float g_dinv[NMAX];

#define FMA_F32X2(d, a, b, c) \
    asm("fma.rn.f32x2 %0, %1, %2, %3;" : "=l"(d) : "l"(a), "l"(b), "l"(c))
#define PACK_DUP(out, f) \
    do { unsigned _u = __float_as_uint(f); \
         asm("mov.b64 %0, {%1, %1};" : "=l"(out) : "r"(_u)); } while (0)
#define UNPACK2(lo, hi, in) \
    asm("mov.b64 {%0, %1}, %2;" : "=r"(lo), "=r"(hi) : "l"(in))

// ---------------------------------------------------------------------------
// Phase 0: zero degree counters; block 0 additionally detects edge dtype
// (int64 stored little-endian with values < 2^31 -> all odd words zero).
// ---------------------------------------------------------------------------
__global__ void init_detect_kernel(const int* __restrict__ edge32, int nwords,
                                   int n) {
    for (int i = blockIdx.x * blockDim.x + threadIdx.x; i < n;
         i += gridDim.x * blockDim.x)
        g_degi[i] = 0;
    if (blockIdx.x == 0) {
        __shared__ int any_nonzero;
        if (threadIdx.x == 0) any_nonzero = 0;
        __syncthreads();
        for (int i = 1 + 2 * threadIdx.x; i < 2048 && i < nwords;
             i += 2 * blockDim.x)
            if (edge32[i] != 0) any_nonzero = 1;
        __syncthreads();
        if (threadIdx.x == 0) g_is64 = any_nonzero ? 0 : 1;
    }
}

// ---------------------------------------------------------------------------
// Phase 1: in-degree count, reading dst directly from the edge buffer
// ---------------------------------------------------------------------------
__global__ void degree_kernel(const void* __restrict__ edge, int E) {
    int is64 = g_is64;
    for (int i = blockIdx.x * blockDim.x + threadIdx.x; i < E;
         i += gridDim.x * blockDim.x) {
        int d = is64 ? (int)((const long long*)edge)[E + i]
                     : ((const int*)edge)[E + i];
        atomicAdd(&g_degi[d], 1);  // no return use -> REDG
    }
}

// ---------------------------------------------------------------------------
// Phase 2: exclusive prefix scan of degrees -> row_start, cursor; also dinv
// ---------------------------------------------------------------------------
__global__ __launch_bounds__(SCAN_T) void scan_kernel(int n) {
    __shared__ int ssum[SCAN_T];
    int tid = threadIdx.x;
    int chunk = (n + SCAN_T - 1) / SCAN_T;
    int b = tid * chunk;
    int e = min(b + chunk, n);
    int s = 0;
    for (int i = b; i < e; i++) s += g_degi[i];
    ssum[tid] = s;
    __syncthreads();
    for (int off = 1; off < SCAN_T; off <<= 1) {
        int t = (tid >= off) ? ssum[tid - off] : 0;
        __syncthreads();
        ssum[tid] += t;
        __syncthreads();
    }
    int run = ssum[tid] - s;
    for (int i = b; i < e; i++) {
        int deg = g_degi[i];
        g_row_start[i] = run;
        g_cursor[i] = run;
        g_dinv[i] = rsqrtf((float)(deg + 1));
        run += deg;
    }
    if (tid == SCAN_T - 1) g_row_start[n] = run;
}

// ---------------------------------------------------------------------------
// Phase 3: counting-sort edges into CSR, reading edge buffer directly
// ---------------------------------------------------------------------------
__global__ void fill_kernel(const void* __restrict__ edge, int E) {
    int is64 = g_is64;
    for (int i = blockIdx.x * blockDim.x + threadIdx.x; i < E;
         i += gridDim.x * blockDim.x) {
        int s, d;
        if (is64) {
            const long long* e64 = (const long long*)edge;
            s = (int)e64[i];
            d = (int)e64[E + i];
        } else {
            const int* e32 = (const int*)edge;
            s = e32[i];
            d = e32[E + i];
        }
        int pos = atomicAdd(&g_cursor[d], 1);
        g_csr_src[pos] = s;
    }
}

// ---------------------------------------------------------------------------
// Phase 4 (fused): gather-aggregate 64 nodes into transposed smem tile, then
// h = A @ W^T + b ; out = x + relu(h), with packed fma.rn.f32x2 mainloop.
// 512 threads: gather = warp per node (4 nodes sequential per warp),
// GEMM = warp owns 4 nodes (2 f32x2 pairs), lane owns 4 features.
// ---------------------------------------------------------------------------
__global__ __launch_bounds__(512, 2) void gather_gemm_kernel(
    const float4* __restrict__ x4, const float* __restrict__ x,
    const float* __restrict__ W, const float* __restrict__ b,
    float* __restrict__ out, int n) {
    __shared__ float Wsm[D * WPAD];  // [k][f]
    __shared__ float Asm[D * APAD];  // [k][node]

    int tid = threadIdx.x;
    int lane = tid & 31;
    int wg = tid >> 5;  // 0..15

    // Load + transpose W: Wsm[k][f] = W[f*128 + k]
    for (int i = tid; i < D * D; i += 512) {
        int f = i >> 7;
        int k = i & 127;
        Wsm[k * WPAD + f] = W[i];
    }

    int node0 = blockIdx.x * 64;

    // ---- gather phase: each warp aggregates 4 nodes ----
    for (int ii = 0; ii < 4; ii++) {
        int nl = wg * 4 + ii;
        int node = node0 + nl;
        float4 r = make_float4(0.f, 0.f, 0.f, 0.f);
        if (node < n) {
            int beg = g_row_start[node];
            int end = g_row_start[node + 1];
            float4 a0 = make_float4(0.f, 0.f, 0.f, 0.f);
            float4 a1 = make_float4(0.f, 0.f, 0.f, 0.f);
            float4 a2 = make_float4(0.f, 0.f, 0.f, 0.f);
            float4 a3 = make_float4(0.f, 0.f, 0.f, 0.f);
            int e = beg;
            for (; e + 4 <= end; e += 4) {
                int s0 = g_csr_src[e + 0];
                int s1 = g_csr_src[e + 1];
                int s2 = g_csr_src[e + 2];
                int s3 = g_csr_src[e + 3];
                float w0 = g_dinv[s0];
                float w1 = g_dinv[s1];
                float w2 = g_dinv[s2];
                float w3 = g_dinv[s3];
                float4 v0 = __ldg(&x4[(size_t)s0 * 32 + lane]);
                float4 v1 = __ldg(&x4[(size_t)s1 * 32 + lane]);
                float4 v2 = __ldg(&x4[(size_t)s2 * 32 + lane]);
                float4 v3 = __ldg(&x4[(size_t)s3 * 32 + lane]);
                a0.x += v0.x * w0; a0.y += v0.y * w0; a0.z += v0.z * w0; a0.w += v0.w * w0;
                a1.x += v1.x * w1; a1.y += v1.y * w1; a1.z += v1.z * w1; a1.w += v1.w * w1;
                a2.x += v2.x * w2; a2.y += v2.y * w2; a2.z += v2.z * w2; a2.w += v2.w * w2;
                a3.x += v3.x * w3; a3.y += v3.y * w3; a3.z += v3.z * w3; a3.w += v3.w * w3;
            }
            for (; e < end; e++) {
                int s = g_csr_src[e];
                float w = g_dinv[s];
                float4 v = __ldg(&x4[(size_t)s * 32 + lane]);
                a0.x += v.x * w; a0.y += v.y * w; a0.z += v.z * w; a0.w += v.w * w;
            }
            float dd = g_dinv[node];
            float4 xv = __ldg(&x4[(size_t)node * 32 + lane]);
            // A = dd * sum + dd^2 * x[node]  (self-loop folded)
            r.x = ((a0.x + a1.x) + (a2.x + a3.x)) * dd + xv.x * dd * dd;
            r.y = ((a0.y + a1.y) + (a2.y + a3.y)) * dd + xv.y * dd * dd;
            r.z = ((a0.z + a1.z) + (a2.z + a3.z)) * dd + xv.z * dd * dd;
            r.w = ((a0.w + a1.w) + (a2.w + a3.w)) * dd + xv.w * dd * dd;
        }
        // transposed store: Asm[k][nl], k = 4*lane + c
        Asm[(4 * lane + 0) * APAD + nl] = r.x;
        Asm[(4 * lane + 1) * APAD + nl] = r.y;
        Asm[(4 * lane + 2) * APAD + nl] = r.z;
        Asm[(4 * lane + 3) * APAD + nl] = r.w;
    }
    __syncthreads();

    // ---- GEMM phase: warp owns nodes node0+4wg..+4 (2 f32x2 pairs) ----
    int f4 = lane * 4;
    ull acc[2][4];
#pragma unroll
    for (int p = 0; p < 2; p++)
#pragma unroll
        for (int c = 0; c < 4; c++) acc[p][c] = 0ull;

#pragma unroll 4
    for (int k = 0; k < D; k++) {
        const ull* arow = reinterpret_cast<const ull*>(&Asm[k * APAD + wg * 4]);
        ull A0 = arow[0], A1 = arow[1];
        float4 w = *reinterpret_cast<const float4*>(&Wsm[k * WPAD + f4]);
        ull W0, W1, W2, W3;
        PACK_DUP(W0, w.x);
        PACK_DUP(W1, w.y);
        PACK_DUP(W2, w.z);
        PACK_DUP(W3, w.w);
        FMA_F32X2(acc[0][0], A0, W0, acc[0][0]);
        FMA_F32X2(acc[0][1], A0, W1, acc[0][1]);
        FMA_F32X2(acc[0][2], A0, W2, acc[0][2]);
        FMA_F32X2(acc[0][3], A0, W3, acc[0][3]);
        FMA_F32X2(acc[1][0], A1, W0, acc[1][0]);
        FMA_F32X2(acc[1][1], A1, W1, acc[1][1]);
        FMA_F32X2(acc[1][2], A1, W2, acc[1][2]);
        FMA_F32X2(acc[1][3], A1, W3, acc[1][3]);
    }

    float4 bb = *reinterpret_cast<const float4*>(&b[f4]);
#pragma unroll
    for (int p = 0; p < 2; p++) {
        unsigned lo0, hi0, lo1, hi1, lo2, hi2, lo3, hi3;
        UNPACK2(lo0, hi0, acc[p][0]);
        UNPACK2(lo1, hi1, acc[p][1]);
        UNPACK2(lo2, hi2, acc[p][2]);
        UNPACK2(lo3, hi3, acc[p][3]);
        int node_e = node0 + wg * 4 + 2 * p;
        if (node_e < n) {
            float4 xv = *reinterpret_cast<const float4*>(&x[(size_t)node_e * D + f4]);
            float4 o;
            o.x = xv.x + fmaxf(__uint_as_float(lo0) + bb.x, 0.f);
            o.y = xv.y + fmaxf(__uint_as_float(lo1) + bb.y, 0.f);
            o.z = xv.z + fmaxf(__uint_as_float(lo2) + bb.z, 0.f);
            o.w = xv.w + fmaxf(__uint_as_float(lo3) + bb.w, 0.f);
            *reinterpret_cast<float4*>(&out[(size_t)node_e * D + f4]) = o;
        }
        int node_o = node_e + 1;
        if (node_o < n) {
            float4 xv = *reinterpret_cast<const float4*>(&x[(size_t)node_o * D + f4]);
            float4 o;
            o.x = xv.x + fmaxf(__uint_as_float(hi0) + bb.x, 0.f);
            o.y = xv.y + fmaxf(__uint_as_float(hi1) + bb.y, 0.f);
            o.z = xv.z + fmaxf(__uint_as_float(hi2) + bb.z, 0.f);
            o.w = xv.w + fmaxf(__uint_as_float(hi3) + bb.w, 0.f);
            *reinterpret_cast<float4*>(&out[(size_t)node_o * D + f4]) = o;
        }
    }
}

// ---------------------------------------------------------------------------
extern "C" void kernel_launch(void* const* d_in, const int* in_sizes, int n_in,
                              void* d_out, int out_size) {
    const float* x = (const float*)d_in[0];
    const void* edge = d_in[1];
    const float* W = (const float*)d_in[2];
    const float* b = (const float*)d_in[3];
    float* out = (float*)d_out;

    int n = in_sizes[0] / D;  // 50000
    int E = in_sizes[1] / 2;  // 1,600,000
    if (E > EMAX) E = EMAX;

    init_detect_kernel<<<64, 256>>>((const int*)edge, in_sizes[1], n);
    degree_kernel<<<(E + 511) / 512, 256>>>(edge, E);
    scan_kernel<<<1, SCAN_T>>>(n);
    fill_kernel<<<(E + 511) / 512, 256>>>(edge, E);
    gather_gemm_kernel<<<(n + 63) / 64, 512>>>((const float4*)x, x, W, b, out, n);
}